// round 6
// baseline (speedup 1.0000x reference)
#include <cuda_runtime.h>

#define FULLMASK 0xffffffffu
typedef unsigned long long u64;

constexpr int MAXN = 50001;
constexpr int MAXE = 1250000;
constexpr int ITERS = 8;        // edge-pairs per warp in score kernel

__device__ int   g_starts[MAXN];
__device__ float g_a1[(MAXN - 1) * 8];          // per-node linear scores [N,8]
__device__ float g_w[(size_t)MAXE * 8];         // per-edge exp-weights [E,8]

// ---------- packed f32x2 helpers ----------
__device__ __forceinline__ u64 pack2(float lo, float hi) {
    u64 r; asm("mov.b64 %0,{%1,%2};" : "=l"(r) : "f"(lo), "f"(hi)); return r;
}
__device__ __forceinline__ u64 splat2(float v) {
    u64 r; asm("mov.b64 %0,{%1,%1};" : "=l"(r) : "f"(v)); return r;
}
__device__ __forceinline__ void unpack2(u64 v, float& lo, float& hi) {
    asm("mov.b64 {%0,%1},%2;" : "=f"(lo), "=f"(hi) : "l"(v));
}
__device__ __forceinline__ u64 fma2(u64 a, u64 b, u64 c) {
    u64 d; asm("fma.rn.f32x2 %0,%1,%2,%3;" : "=l"(d) : "l"(a), "l"(b), "l"(c)); return d;
}
__device__ __forceinline__ u64 add2(u64 a, u64 b) {
    u64 d; asm("add.rn.f32x2 %0,%1,%2;" : "=l"(d) : "l"(a), "l"(b)); return d;
}

__device__ __forceinline__ float elu1(float x) {
    return x > 0.0f ? x : (__expf(x) - 1.0f);
}

// ---------- kernel 0: CSR row starts from sorted seg ----------
__global__ void build_starts_kernel(const int* __restrict__ seg, int N, int E) {
    int e = blockIdx.x * blockDim.x + threadIdx.x;
    if (e >= E) return;
    int s = seg[e];
    int p = (e == 0) ? -1 : seg[e - 1];
    for (int n = p + 1; n <= s; ++n) g_starts[n] = e;
    if (e == E - 1)
        for (int n = s + 1; n <= N; ++n) g_starts[n] = E;
}

// 32-lane reduce of 8 partials with head splitting; lane ends with head lane>>2
__device__ __forceinline__ float reduce8_32(const float p[8], int lane) {
    bool b4 = (lane & 16) != 0;
    float q[4];
#pragma unroll
    for (int j = 0; j < 4; ++j) {
        float send = b4 ? p[j] : p[j + 4];
        float recv = __shfl_xor_sync(FULLMASK, send, 16);
        q[j] = (b4 ? p[j + 4] : p[j]) + recv;
    }
    bool b3 = (lane & 8) != 0;
    float r[2];
#pragma unroll
    for (int j = 0; j < 2; ++j) {
        float send = b3 ? q[j] : q[j + 2];
        float recv = __shfl_xor_sync(FULLMASK, send, 8);
        r[j] = (b3 ? q[j + 2] : q[j]) + recv;
    }
    bool b2 = (lane & 4) != 0;
    float send = b2 ? r[0] : r[1];
    float recv = __shfl_xor_sync(FULLMASK, send, 4);
    float s = (b2 ? r[1] : r[0]) + recv;
    s += __shfl_xor_sync(FULLMASK, s, 2);
    s += __shfl_xor_sync(FULLMASK, s, 1);
    return s;
}

// ---------- kernel 1: a1[n,h] = features[n] . attn1[h]  (warp per node) ----------
__global__ __launch_bounds__(256, 8)
void a1_kernel(const float* __restrict__ features,
               const float* __restrict__ attn1, int N) {
    const int lane = threadIdx.x & 31;
    const int n = blockIdx.x * 8 + (threadIdx.x >> 5);
    if (n >= N) return;
    float2 f = *(const float2*)(features + (size_t)n * 64 + 2 * lane);
    float p1[8];
#pragma unroll
    for (int h = 0; h < 8; ++h) {
        float2 a = *(const float2*)(attn1 + h * 64 + 2 * lane);
        p1[h] = f.x * a.x + f.y * a.y;
    }
    float v = reduce8_32(p1, lane);
    if ((lane & 3) == 0) g_a1[n * 8 + (lane >> 2)] = v;
}

// ---------- kernel 2: edge-parallel scores w = exp(leaky(a1+a2)) ----------
// warp handles ITERS edge-pairs; 16 lanes per edge (lane: g=slot, i=dim quad)
__global__ __launch_bounds__(256, 4)
void score_kernel(const float* __restrict__ emb,
                  const float* __restrict__ attn2,
                  const int*   __restrict__ seg, int E) {
    const int lane = threadIdx.x & 31;
    const int warp = blockIdx.x * 8 + (threadIdx.x >> 5);
    const int g = lane >> 4;
    const int i = lane & 15;
    const int head = i >> 1;

    // attn2 resident in registers: 8 heads x this lane's dim quad
    u64 w2r[8][2];
    const float4* __restrict__ a2f4 = (const float4*)attn2;
#pragma unroll
    for (int h = 0; h < 8; ++h) {
        float4 t = a2f4[h * 16 + i];
        w2r[h][0] = pack2(t.x, t.y);
        w2r[h][1] = pack2(t.z, t.w);
    }

    const float4* __restrict__ ef4 = (const float4*)emb;
    const int P = (E + 1) >> 1;
    const u64 Z = 0ull;

#pragma unroll 2
    for (int t = 0; t < ITERS; ++t) {
        int p = warp * ITERS + t;
        if (p >= P) break;
        int e = 2 * p + g;
        bool val = e < E;
        int ec = min(e, E - 1);

        float4 F = ef4[(size_t)ec * 16 + i];
        int sg = seg[ec];
        float a1v = __ldg(g_a1 + sg * 8 + head);

        float pp[8];
#pragma unroll
        for (int h = 0; h < 8; ++h) {
            u64 tt = fma2(pack2(F.x, F.y), w2r[h][0], Z);
            tt = fma2(pack2(F.z, F.w), w2r[h][1], tt);
            float lo, hi; unpack2(tt, lo, hi);
            pp[h] = lo + hi;
        }

        // 16-lane head-splitting tree: lane i -> head i>>1 (dup over i&1)
        bool b3 = (i & 8) != 0;
        float q[4];
#pragma unroll
        for (int j = 0; j < 4; ++j) {
            float send = b3 ? pp[j] : pp[j + 4];
            float recv = __shfl_xor_sync(FULLMASK, send, 8);
            q[j] = (b3 ? pp[j + 4] : pp[j]) + recv;
        }
        bool b2 = (i & 4) != 0;
        float r[2];
#pragma unroll
        for (int j = 0; j < 2; ++j) {
            float send = b2 ? q[j] : q[j + 2];
            float recv = __shfl_xor_sync(FULLMASK, send, 4);
            r[j] = (b2 ? q[j + 2] : q[j]) + recv;
        }
        bool b1 = (i & 2) != 0;
        float send = b1 ? r[0] : r[1];
        float recv = __shfl_xor_sync(FULLMASK, send, 2);
        float s = (b1 ? r[1] : r[0]) + recv;
        s += __shfl_xor_sync(FULLMASK, s, 1);

        float sc = s + a1v;
        sc = fmaxf(sc, 0.2f * sc);                 // leaky relu
        float w = __expf(sc);                      // no-max softmax (bounded scores)
        if (val && !(i & 1)) g_w[(size_t)e * 8 + head] = w;
    }
}

// ---------- kernel 3: aggregation (warp per node, shuffle-free) ----------
__global__ __launch_bounds__(256, 6)
void agg_kernel(const float* __restrict__ emb,
                float*       __restrict__ out, int N) {
    const int lane = threadIdx.x & 31;
    const int n = blockIdx.x * 8 + (threadIdx.x >> 5);
    if (n >= N) return;

    const int s0 = g_starts[n];
    const int e0 = g_starts[n + 1];

    const float2* __restrict__ emb2 = (const float2*)emb;
    const float4* __restrict__ wf4  = (const float4*)g_w;

    const u64 Z = 0ull;
    u64 accx[4], accy[4], dn[4];
#pragma unroll
    for (int hp = 0; hp < 4; ++hp) { accx[hp] = Z; accy[hp] = Z; dn[hp] = Z; }

    auto body = [&](int e) {
        float2 c  = emb2[(size_t)e * 32 + lane];       // coalesced 256B / warp
        float4 wA = wf4[(size_t)e * 2];                // uniform -> broadcast
        float4 wB = wf4[(size_t)e * 2 + 1];
        u64 w01 = pack2(wA.x, wA.y), w23 = pack2(wA.z, wA.w);
        u64 w45 = pack2(wB.x, wB.y), w67 = pack2(wB.z, wB.w);
        dn[0] = add2(dn[0], w01);
        dn[1] = add2(dn[1], w23);
        dn[2] = add2(dn[2], w45);
        dn[3] = add2(dn[3], w67);
        u64 cx = splat2(c.x), cy = splat2(c.y);
        accx[0] = fma2(w01, cx, accx[0]);  accy[0] = fma2(w01, cy, accy[0]);
        accx[1] = fma2(w23, cx, accx[1]);  accy[1] = fma2(w23, cy, accy[1]);
        accx[2] = fma2(w45, cx, accx[2]);  accy[2] = fma2(w45, cy, accy[2]);
        accx[3] = fma2(w67, cx, accx[3]);  accy[3] = fma2(w67, cy, accy[3]);
    };

    int e = s0;
    for (; e + 1 < e0; e += 2) { body(e); body(e + 1); }   // MLP=2 via interleave
    if (e < e0) body(e);

    // finalize: denom identical in every lane (broadcast accumulation)
    float* op = out + (size_t)n * 512 + 2 * lane;
#pragma unroll
    for (int hp = 0; hp < 4; ++hp) {
        float d0, d1; unpack2(dn[hp], d0, d1);
        float i0 = d0 > 0.0f ? __frcp_rn(d0) : 1.0f;
        float i1 = d1 > 0.0f ? __frcp_rn(d1) : 1.0f;
        float x0, x1, y0, y1;
        unpack2(accx[hp], x0, x1);
        unpack2(accy[hp], y0, y1);
        *(float2*)(op + (2 * hp)     * 64) = make_float2(elu1(x0 * i0), elu1(y0 * i0));
        *(float2*)(op + (2 * hp + 1) * 64) = make_float2(elu1(x1 * i1), elu1(y1 * i1));
    }
}

extern "C" void kernel_launch(void* const* d_in, const int* in_sizes, int n_in,
                              void* d_out, int out_size) {
    const float* features = (const float*)d_in[0];
    const float* emb      = (const float*)d_in[1];
    const float* attn1    = (const float*)d_in[2];
    const float* attn2    = (const float*)d_in[3];
    const int*   seg      = (const int*)d_in[4];
    float* out = (float*)d_out;

    int N = in_sizes[0] / 64;    // 50000
    int E = in_sizes[4];         // 1250000

    build_starts_kernel<<<(E + 255) / 256, 256>>>(seg, N, E);
    a1_kernel<<<(N + 7) / 8, 256>>>(features, attn1, N);

    int P = (E + 1) / 2;
    int warpsNeeded = (P + ITERS - 1) / ITERS;
    score_kernel<<<(warpsNeeded + 7) / 8, 256>>>(emb, attn2, seg, E);

    agg_kernel<<<(N + 7) / 8, 256>>>(emb, out, N);
}

// round 8
// speedup vs baseline: 1.8329x; 1.8329x over previous
#include <cuda_runtime.h>

#define FULLMASK 0xffffffffu
typedef unsigned long long u64;

constexpr int NPB  = 4;          // warps (nodes) per block
constexpr int MAXN = 50001;

__device__ int g_starts[MAXN];   // CSR row starts

// ---------- packed f32x2 helpers ----------
__device__ __forceinline__ u64 pack2(float lo, float hi) {
    u64 r; asm("mov.b64 %0,{%1,%2};" : "=l"(r) : "f"(lo), "f"(hi)); return r;
}
__device__ __forceinline__ u64 splat2(float v) {
    u64 r; asm("mov.b64 %0,{%1,%1};" : "=l"(r) : "f"(v)); return r;
}
__device__ __forceinline__ void unpack2(u64 v, float& lo, float& hi) {
    asm("mov.b64 {%0,%1},%2;" : "=f"(lo), "=f"(hi) : "l"(v));
}
__device__ __forceinline__ u64 fma2(u64 a, u64 b, u64 c) {
    u64 d; asm("fma.rn.f32x2 %0,%1,%2,%3;" : "=l"(d) : "l"(a), "l"(b), "l"(c)); return d;
}

// ---------- kernel 0: build row starts from sorted seg ----------
__global__ void build_starts_kernel(const int* __restrict__ seg, int N, int E) {
    int e = blockIdx.x * blockDim.x + threadIdx.x;
    if (e >= E) return;
    int s = seg[e];
    int p = (e == 0) ? -1 : seg[e - 1];
    for (int n = p + 1; n <= s; ++n) g_starts[n] = e;
    if (e == E - 1)
        for (int n = s + 1; n <= N; ++n) g_starts[n] = E;
}

// 32-lane reduce of 8 partials with head splitting; lane ends with head lane>>2
__device__ __forceinline__ float reduce8_32(const float p[8], int lane) {
    bool b4 = (lane & 16) != 0;
    float q[4];
#pragma unroll
    for (int j = 0; j < 4; ++j) {
        float send = b4 ? p[j] : p[j + 4];
        float recv = __shfl_xor_sync(FULLMASK, send, 16);
        q[j] = (b4 ? p[j + 4] : p[j]) + recv;
    }
    bool b3 = (lane & 8) != 0;
    float r[2];
#pragma unroll
    for (int j = 0; j < 2; ++j) {
        float send = b3 ? q[j] : q[j + 2];
        float recv = __shfl_xor_sync(FULLMASK, send, 8);
        r[j] = (b3 ? q[j + 2] : q[j]) + recv;
    }
    bool b2 = (lane & 4) != 0;
    float send = b2 ? r[0] : r[1];
    float recv = __shfl_xor_sync(FULLMASK, send, 4);
    float s = (b2 ? r[1] : r[0]) + recv;
    s += __shfl_xor_sync(FULLMASK, s, 2);
    s += __shfl_xor_sync(FULLMASK, s, 1);
    return s;
}

__device__ __forceinline__ float elu1(float x) {
    return x > 0.0f ? x : (__expf(x) - 1.0f);
}

// ---------- main fused kernel: warp/node, 4 edges per iter (2 interleaved pairs) ----------
__global__ __launch_bounds__(128, 5)
void gat_agg_kernel(const float* __restrict__ features,
                    const float* __restrict__ emb,
                    const float* __restrict__ attn1,
                    const float* __restrict__ attn2,
                    float*       __restrict__ out,
                    int N)
{
    const int lane = threadIdx.x & 31;
    const int wid  = threadIdx.x >> 5;
    const int n    = blockIdx.x * NPB + wid;
    if (n >= N) return;

    const int g    = lane >> 4;        // edge slot within pair (0/1)
    const int i    = lane & 15;        // dim-quad index: dims [4i, 4i+4)
    const int head = i >> 1;           // score head this lane ends with (dup over i&1)

    const int s0 = g_starts[n];
    const int e0 = g_starts[n + 1];

    // ---- attn2 resident in registers: 8 heads x this lane's dim quad ----
    u64 w2r[8][2];
    const float4* __restrict__ a2f4 = (const float4*)attn2;
#pragma unroll
    for (int h = 0; h < 8; ++h) {
        float4 t = a2f4[h * 16 + i];
        w2r[h][0] = pack2(t.x, t.y);
        w2r[h][1] = pack2(t.z, t.w);
    }

    // ---- a1 for this lane's score head (once per node) ----
    float a1_i;
    {
        float2 f = *(const float2*)(features + (size_t)n * 64 + 2 * lane);
        float p1[8];
#pragma unroll
        for (int h = 0; h < 8; ++h) {
            float2 a = *(const float2*)(attn1 + h * 64 + 2 * lane);
            p1[h] = f.x * a.x + f.y * a.y;
        }
        float a1h = reduce8_32(p1, lane);             // lane -> head lane>>2
        a1_i = __shfl_sync(FULLMASK, a1h, 4 * head);
    }

    const float4* __restrict__ ef4 = (const float4*)emb;
    const u64 Z = 0ull;

    u64 acc[4][2];                                    // heads [4g,4g+4) x dim pairs
#pragma unroll
    for (int hp = 0; hp < 4; ++hp) { acc[hp][0] = Z; acc[hp][1] = Z; }
    float dn = 0.0f;

    const int nIter = (e0 - s0 + 3) >> 2;
    const bool b3 = (i & 8) != 0;
    const bool b2 = (i & 4) != 0;
    const bool b1 = (i & 2) != 0;

    for (int t = 0; t < nIter; ++t) {
        const int base = s0 + 4 * t;
        const int eA = base + g;
        const int eB = base + 2 + g;
        const bool vA = eA < e0;
        const bool vB = eB < e0;

        // both loads issued up-front (MLP=2)
        float4 FA = ef4[(size_t)min(eA, e0 - 1) * 16 + i];
        float4 FB = ef4[(size_t)min(eB, e0 - 1) * 16 + i];

        u64 ea0 = pack2(FA.x, FA.y), ea1 = pack2(FA.z, FA.w);
        u64 eb0 = pack2(FB.x, FB.y), eb1 = pack2(FB.z, FB.w);

        // ---- phase A: 8 head-partials per pair (independent chains) ----
        float pA[8], pB[8];
#pragma unroll
        for (int h = 0; h < 8; ++h) {
            u64 tA = fma2(ea0, w2r[h][0], Z);
            u64 tB = fma2(eb0, w2r[h][0], Z);
            tA = fma2(ea1, w2r[h][1], tA);
            tB = fma2(eb1, w2r[h][1], tB);
            float lA, hA, lB, hB;
            unpack2(tA, lA, hA); unpack2(tB, lB, hB);
            pA[h] = lA + hA; pB[h] = lB + hB;
        }

        // ---- interleaved 16-lane head-splitting trees (A/B alternate) ----
        float qA[4], qB[4];
#pragma unroll
        for (int j = 0; j < 4; ++j) {
            float sendA = b3 ? pA[j] : pA[j + 4];
            float sendB = b3 ? pB[j] : pB[j + 4];
            float recvA = __shfl_xor_sync(FULLMASK, sendA, 8);
            float recvB = __shfl_xor_sync(FULLMASK, sendB, 8);
            qA[j] = (b3 ? pA[j + 4] : pA[j]) + recvA;
            qB[j] = (b3 ? pB[j + 4] : pB[j]) + recvB;
        }
        float rA[2], rB[2];
#pragma unroll
        for (int j = 0; j < 2; ++j) {
            float sendA = b2 ? qA[j] : qA[j + 2];
            float sendB = b2 ? qB[j] : qB[j + 2];
            float recvA = __shfl_xor_sync(FULLMASK, sendA, 4);
            float recvB = __shfl_xor_sync(FULLMASK, sendB, 4);
            rA[j] = (b2 ? qA[j + 2] : qA[j]) + recvA;
            rB[j] = (b2 ? qB[j + 2] : qB[j]) + recvB;
        }
        {
            float sendA = b1 ? rA[0] : rA[1];
            float sendB = b1 ? rB[0] : rB[1];
            float recvA = __shfl_xor_sync(FULLMASK, sendA, 2);
            float recvB = __shfl_xor_sync(FULLMASK, sendB, 2);
            rA[0] = (b1 ? rA[1] : rA[0]) + recvA;
            rB[0] = (b1 ? rB[1] : rB[0]) + recvB;
        }
        rA[0] += __shfl_xor_sync(FULLMASK, rA[0], 1);   // exact dup over i&1
        rB[0] += __shfl_xor_sync(FULLMASK, rB[0], 1);

        float scA = rA[0] + a1_i;
        float scB = rB[0] + a1_i;
        scA = fmaxf(scA, 0.2f * scA);                   // leaky relu
        scB = fmaxf(scB, 0.2f * scB);
        float wA = vA ? __expf(scA) : 0.0f;             // no-max softmax (bounded)
        float wB = vB ? __expf(scB) : 0.0f;
        dn += wA + wB;

        // ---- phase B: quad exchange + rank-4 update from registers ----
        float oxA = __shfl_xor_sync(FULLMASK, FA.x, 16);
        float oxB = __shfl_xor_sync(FULLMASK, FB.x, 16);
        float oyA = __shfl_xor_sync(FULLMASK, FA.y, 16);
        float oyB = __shfl_xor_sync(FULLMASK, FB.y, 16);
        float ozA = __shfl_xor_sync(FULLMASK, FA.z, 16);
        float ozB = __shfl_xor_sync(FULLMASK, FB.z, 16);
        float owA = __shfl_xor_sync(FULLMASK, FA.w, 16);
        float owB = __shfl_xor_sync(FULLMASK, FB.w, 16);
        u64 oa0 = pack2(oxA, oyA), oa1 = pack2(ozA, owA);
        u64 ob0 = pack2(oxB, oyB), ob1 = pack2(ozB, owB);

#pragma unroll
        for (int hp = 0; hp < 4; ++hp) {
            // weight of own-slot edge for head 4g+hp at lane 24g+2hp;
            // other-slot edge at lane 16-8g+2hp
            float wOwnA = __shfl_sync(FULLMASK, wA, 24 * g + 2 * hp);
            float wOthA = __shfl_sync(FULLMASK, wA, 16 - 8 * g + 2 * hp);
            float wOwnB = __shfl_sync(FULLMASK, wB, 24 * g + 2 * hp);
            float wOthB = __shfl_sync(FULLMASK, wB, 16 - 8 * g + 2 * hp);
            u64 sOwnA = splat2(wOwnA), sOthA = splat2(wOthA);
            u64 sOwnB = splat2(wOwnB), sOthB = splat2(wOthB);
            acc[hp][0] = fma2(ea0, sOwnA, acc[hp][0]);
            acc[hp][1] = fma2(ea1, sOwnA, acc[hp][1]);
            acc[hp][0] = fma2(oa0, sOthA, acc[hp][0]);
            acc[hp][1] = fma2(oa1, sOthA, acc[hp][1]);
            acc[hp][0] = fma2(eb0, sOwnB, acc[hp][0]);
            acc[hp][1] = fma2(eb1, sOwnB, acc[hp][1]);
            acc[hp][0] = fma2(ob0, sOthB, acc[hp][0]);
            acc[hp][1] = fma2(ob1, sOthB, acc[hp][1]);
        }
    }

    // ---- denominator: dup lanes bit-identical -> xor1+xor16 gives exactly 2x ----
    dn += __shfl_xor_sync(FULLMASK, dn, 1);
    dn += __shfl_xor_sync(FULLMASK, dn, 16);
    float inv = dn > 0.0f ? 2.0f * __frcp_rn(dn) : 1.0f;

    // ---- finalize: normalize, ELU, store ----
    float* op = out + (size_t)n * 512;
#pragma unroll
    for (int hp = 0; hp < 4; ++hp) {
        float ih = __shfl_sync(FULLMASK, inv, 8 * g + 2 * hp);
        float v0, v1, v2, v3;
        unpack2(acc[hp][0], v0, v1);
        unpack2(acc[hp][1], v2, v3);
        float4 o;
        o.x = elu1(v0 * ih);
        o.y = elu1(v1 * ih);
        o.z = elu1(v2 * ih);
        o.w = elu1(v3 * ih);
        *(float4*)(op + (4 * g + hp) * 64 + 4 * i) = o;
    }
}

extern "C" void kernel_launch(void* const* d_in, const int* in_sizes, int n_in,
                              void* d_out, int out_size) {
    const float* features = (const float*)d_in[0];
    const float* emb      = (const float*)d_in[1];
    const float* attn1    = (const float*)d_in[2];
    const float* attn2    = (const float*)d_in[3];
    const int*   seg      = (const int*)d_in[4];
    float* out = (float*)d_out;

    int N = in_sizes[0] / 64;    // 50000
    int E = in_sizes[4];         // 1250000

    build_starts_kernel<<<(E + 255) / 256, 256>>>(seg, N, E);

    int blocks = (N + NPB - 1) / NPB;
    gat_agg_kernel<<<blocks, NPB * 32>>>(features, emb, attn1, attn2, out, N);
}

// round 9
// speedup vs baseline: 2.0110x; 1.0971x over previous
#include <cuda_runtime.h>

#define FULLMASK 0xffffffffu
typedef unsigned long long u64;

constexpr int NPB  = 4;           // nodes (=warps) per block
constexpr int CH   = 192;         // edge-chunk capacity (multiple of 16); 4 nodes avg 100, 9+ sigma
constexpr int MAXN = 50001;

__device__ int   g_starts[MAXN];
__device__ float g_a1[(MAXN - 1) * 8];

// ---------- packed f32x2 helpers ----------
__device__ __forceinline__ u64 pack2(float lo, float hi) {
    u64 r; asm("mov.b64 %0,{%1,%2};" : "=l"(r) : "f"(lo), "f"(hi)); return r;
}
__device__ __forceinline__ u64 splat2(float v) {
    u64 r; asm("mov.b64 %0,{%1,%1};" : "=l"(r) : "f"(v)); return r;
}
__device__ __forceinline__ void unpack2(u64 v, float& lo, float& hi) {
    asm("mov.b64 {%0,%1},%2;" : "=f"(lo), "=f"(hi) : "l"(v));
}
__device__ __forceinline__ u64 fma2(u64 a, u64 b, u64 c) {
    u64 d; asm("fma.rn.f32x2 %0,%1,%2,%3;" : "=l"(d) : "l"(a), "l"(b), "l"(c)); return d;
}
__device__ __forceinline__ u64 add2(u64 a, u64 b) {
    u64 d; asm("add.rn.f32x2 %0,%1,%2;" : "=l"(d) : "l"(a), "l"(b)); return d;
}
__device__ __forceinline__ float elu1(float x) {
    return x > 0.0f ? x : (__expf(x) - 1.0f);
}

// ---------- kernel 0: CSR row starts ----------
__global__ void build_starts_kernel(const int* __restrict__ seg, int N, int E) {
    int e = blockIdx.x * blockDim.x + threadIdx.x;
    if (e >= E) return;
    int s = seg[e];
    int p = (e == 0) ? -1 : seg[e - 1];
    for (int n = p + 1; n <= s; ++n) g_starts[n] = e;
    if (e == E - 1)
        for (int n = s + 1; n <= N; ++n) g_starts[n] = E;
}

// 32-lane reduce of 8 partials; lane ends with head lane>>2
__device__ __forceinline__ float reduce8_32(const float p[8], int lane) {
    bool b4 = (lane & 16) != 0;
    float q[4];
#pragma unroll
    for (int j = 0; j < 4; ++j) {
        float send = b4 ? p[j] : p[j + 4];
        float recv = __shfl_xor_sync(FULLMASK, send, 16);
        q[j] = (b4 ? p[j + 4] : p[j]) + recv;
    }
    bool b3 = (lane & 8) != 0;
    float r[2];
#pragma unroll
    for (int j = 0; j < 2; ++j) {
        float send = b3 ? q[j] : q[j + 2];
        float recv = __shfl_xor_sync(FULLMASK, send, 8);
        r[j] = (b3 ? q[j + 2] : q[j]) + recv;
    }
    bool b2 = (lane & 4) != 0;
    float send = b2 ? r[0] : r[1];
    float recv = __shfl_xor_sync(FULLMASK, send, 4);
    float s = (b2 ? r[1] : r[0]) + recv;
    s += __shfl_xor_sync(FULLMASK, s, 2);
    s += __shfl_xor_sync(FULLMASK, s, 1);
    return s;
}

// ---------- kernel 1: a1[n,h] = features[n] . attn1[h] ----------
__global__ __launch_bounds__(256, 8)
void a1_kernel(const float* __restrict__ features,
               const float* __restrict__ attn1, int N) {
    const int lane = threadIdx.x & 31;
    const int n = blockIdx.x * 8 + (threadIdx.x >> 5);
    if (n >= N) return;
    float2 f = *(const float2*)(features + (size_t)n * 64 + 2 * lane);
    float p1[8];
#pragma unroll
    for (int h = 0; h < 8; ++h) {
        float2 a = *(const float2*)(attn1 + h * 64 + 2 * lane);
        p1[h] = f.x * a.x + f.y * a.y;
    }
    float v = reduce8_32(p1, lane);
    if ((lane & 3) == 0) g_a1[n * 8 + (lane >> 2)] = v;
}

// ---------- main kernel: block = 4 warps = 4 nodes; two-phase, shuffle-free ----------
__global__ __launch_bounds__(128, 6)
void gat_main_kernel(const float* __restrict__ emb,
                     const float* __restrict__ attn2,
                     const int*   __restrict__ seg,
                     float*       __restrict__ out,
                     int N)
{
    __shared__ float4 s_stage[NPB][16][16];   // [warp][edge][chunk], chunk index swizzled (16KB)
    __shared__ float  s_w[CH * 8];            // per-edge weights (6KB)
    __shared__ float4 s_a2[8][16];            // attn2 [head][chunk16B] (2KB)

    const int tid  = threadIdx.x;
    const int lane = tid & 31;
    const int wid  = tid >> 5;

    // attn2 -> smem (128 float4s, one per thread)
    {
        const float4* a2f4 = (const float4*)attn2;
        s_a2[tid >> 4][tid & 15] = a2f4[tid];
    }

    const int nb0 = blockIdx.x * NPB;
    if (nb0 >= N) return;
    const int eStart = g_starts[nb0];
    const int eEnd   = g_starts[min(nb0 + NPB, N)];

    const int n  = nb0 + wid;                 // this warp's node
    const bool nodeValid = n < N;
    const int s0 = nodeValid ? g_starts[n]     : 0;
    const int e0 = nodeValid ? g_starts[n + 1] : 0;

    const float4* __restrict__ ef4  = (const float4*)emb;
    const float2* __restrict__ emb2 = (const float2*)emb;

    const u64 Z = 0ull;
    u64 accx[4], accy[4], dnp[4];             // head-pair packed accumulators
#pragma unroll
    for (int hp = 0; hp < 4; ++hp) { accx[hp] = Z; accy[hp] = Z; dnp[hp] = Z; }

    __syncthreads();                          // s_a2 ready

    const int el = lane & 15;                 // score phase: this lane's edge slot
    const int hh = lane >> 4;                 //              head half (0:0-3, 1:4-7)

    for (int cb = eStart; cb < eEnd; cb += CH) {
        const int ce = min(cb + CH, eEnd);
        const int nSweeps = (ce - cb + 15) >> 4;

        // ======== score phase: warp-strided sweeps of 16 edges ========
        for (int s = wid; s < nSweeps; s += NPB) {
            const int eb = cb + s * 16;

            // fill staging: 16 edges x 256B, coalesced, swizzled store
#pragma unroll
            for (int it = 0; it < 8; ++it) {
                int idx = it * 32 + lane;
                int e = idx >> 4, c = idx & 15;
                int ge = min(eb + e, eEnd - 1);
                s_stage[wid][e][c ^ e] = ef4[(size_t)ge * 16 + c];
            }
            __syncwarp();

            // in-lane dot: edge el, heads [4hh, 4hh+4), all 64 dims
            const int ge  = eb + el;
            const int gec = min(ge, eEnd - 1);
            const int sg  = seg[gec];
            float4 a1v = *(const float4*)(g_a1 + sg * 8 + hh * 4);

            u64 d0 = Z, d1 = Z, d2 = Z, d3 = Z;
#pragma unroll
            for (int c = 0; c < 16; ++c) {
                float4 ev = s_stage[wid][el][c ^ el];
                u64 ep0 = pack2(ev.x, ev.y), ep1 = pack2(ev.z, ev.w);
                float4 a20 = s_a2[hh * 4 + 0][c];
                float4 a21 = s_a2[hh * 4 + 1][c];
                float4 a22 = s_a2[hh * 4 + 2][c];
                float4 a23 = s_a2[hh * 4 + 3][c];
                d0 = fma2(ep0, pack2(a20.x, a20.y), d0);
                d1 = fma2(ep0, pack2(a21.x, a21.y), d1);
                d2 = fma2(ep0, pack2(a22.x, a22.y), d2);
                d3 = fma2(ep0, pack2(a23.x, a23.y), d3);
                d0 = fma2(ep1, pack2(a20.z, a20.w), d0);
                d1 = fma2(ep1, pack2(a21.z, a21.w), d1);
                d2 = fma2(ep1, pack2(a22.z, a22.w), d2);
                d3 = fma2(ep1, pack2(a23.z, a23.w), d3);
            }
            float l0, h0, l1, h1, l2, h2, l3, h3;
            unpack2(d0, l0, h0); unpack2(d1, l1, h1);
            unpack2(d2, l2, h2); unpack2(d3, l3, h3);
            float sc0 = a1v.x + (l0 + h0);
            float sc1 = a1v.y + (l1 + h1);
            float sc2 = a1v.z + (l2 + h2);
            float sc3 = a1v.w + (l3 + h3);
            sc0 = fmaxf(sc0, 0.2f * sc0);
            sc1 = fmaxf(sc1, 0.2f * sc1);
            sc2 = fmaxf(sc2, 0.2f * sc2);
            sc3 = fmaxf(sc3, 0.2f * sc3);
            // no-max softmax: scores bounded, exp cannot overflow fp32
            float4 wv = make_float4(__expf(sc0), __expf(sc1), __expf(sc2), __expf(sc3));
            // slot (s*16+el) unique; out-of-range slots never read by agg
            *(float4*)(s_w + (s * 16 + el) * 8 + hh * 4) = wv;
        }
        __syncthreads();

        // ======== agg phase: warp per node, edges in [cb, ce) ========
        if (nodeValid) {
            const int lo  = max(s0, cb);
            const int hiE = min(e0, ce);
            for (int e = lo; e < hiE; ++e) {
                const int eloc = e - cb;
                float2 cv = emb2[(size_t)e * 32 + lane];           // L1-hot (just staged)
                float4 wa = *(const float4*)(s_w + eloc * 8);      // broadcast LDS
                float4 wb = *(const float4*)(s_w + eloc * 8 + 4);
                u64 w01 = pack2(wa.x, wa.y), w23 = pack2(wa.z, wa.w);
                u64 w45 = pack2(wb.x, wb.y), w67 = pack2(wb.z, wb.w);
                dnp[0] = add2(dnp[0], w01);
                dnp[1] = add2(dnp[1], w23);
                dnp[2] = add2(dnp[2], w45);
                dnp[3] = add2(dnp[3], w67);
                u64 cx = splat2(cv.x), cy = splat2(cv.y);
                accx[0] = fma2(w01, cx, accx[0]);  accy[0] = fma2(w01, cy, accy[0]);
                accx[1] = fma2(w23, cx, accx[1]);  accy[1] = fma2(w23, cy, accy[1]);
                accx[2] = fma2(w45, cx, accx[2]);  accy[2] = fma2(w45, cy, accy[2]);
                accx[3] = fma2(w67, cx, accx[3]);  accy[3] = fma2(w67, cy, accy[3]);
            }
        }
        __syncthreads();                       // s_w reused next chunk
    }

    // ======== finalize: normalize, ELU, store ========
    if (nodeValid) {
        float* op = out + (size_t)n * 512 + 2 * lane;
#pragma unroll
        for (int hp = 0; hp < 4; ++hp) {
            float dA, dB; unpack2(dnp[hp], dA, dB);
            float iA = dA > 0.0f ? __frcp_rn(dA) : 1.0f;
            float iB = dB > 0.0f ? __frcp_rn(dB) : 1.0f;
            float xA, xB, yA, yB;
            unpack2(accx[hp], xA, xB);
            unpack2(accy[hp], yA, yB);
            *(float2*)(op + (2 * hp)     * 64) = make_float2(elu1(xA * iA), elu1(yA * iA));
            *(float2*)(op + (2 * hp + 1) * 64) = make_float2(elu1(xB * iB), elu1(yB * iB));
        }
    }
}

extern "C" void kernel_launch(void* const* d_in, const int* in_sizes, int n_in,
                              void* d_out, int out_size) {
    const float* features = (const float*)d_in[0];
    const float* emb      = (const float*)d_in[1];
    const float* attn1    = (const float*)d_in[2];
    const float* attn2    = (const float*)d_in[3];
    const int*   seg      = (const int*)d_in[4];
    float* out = (float*)d_out;

    int N = in_sizes[0] / 64;    // 50000
    int E = in_sizes[4];         // 1250000

    build_starts_kernel<<<(E + 255) / 256, 256>>>(seg, N, E);
    a1_kernel<<<(N + 7) / 8, 256>>>(features, attn1, N);

    int blocks = (N + NPB - 1) / NPB;
    gat_main_kernel<<<blocks, NPB * 32>>>(emb, attn2, seg, out, N);
}